// round 15
// baseline (speedup 1.0000x reference)
#include <cuda_runtime.h>
#include <cuda_bf16.h>
#include <cuda_fp16.h>
#include <math.h>
#include <cstdint>

// ----------------------------------------------------------------------------
// Problem constants
// ----------------------------------------------------------------------------
#define BB   16
#define MM   128
#define LL   32
#define SS   512
#define DD   768
#define HH   12
#define HD   64
#define DFF  3072
#define NL   4
#define NE   50000
#define ROWS (BB*MM)          // 2048
#define KPAD 112              // padded K for classifier stage 2

typedef unsigned long long ull;
typedef unsigned int u32;
typedef __nv_bfloat16 bf16;

// weight scratch offsets (elements)
#define OW_QKV  0ULL
#define OW_OUT  7077888ULL
#define OW_FF1  9437184ULL
#define OW_FF2  18874368ULL
#define OW_CLS1 28311552ULL
#define OW_CLS2 28388352ULL
#define NW_TOT  (28388352ULL + 50000ULL*KPAD)

// ----------------------------------------------------------------------------
// Device scratch (static allocation — no cudaMalloc allowed)
// ----------------------------------------------------------------------------
__device__ float g_x [ROWS*DD];
__device__ float g_tmp[ROWS*DFF];            // split-K partials (2 x ROWS*DD)
__device__ __align__(256) bf16 g_wh[NW_TOT];
__device__ __align__(256) bf16 g_wl[NW_TOT];
__device__ __align__(256) bf16 g_ah[ROWS*DFF];
__device__ __align__(256) bf16 g_al[ROWS*DFF];
__device__ __align__(256) bf16 g_bh[ROWS*DFF];
__device__ __align__(256) bf16 g_bl[ROWS*DFF];

// ----------------------------------------------------------------------------
// PTX helpers
// ----------------------------------------------------------------------------
__device__ __forceinline__ u32 smem_u32(const void* p)
{
    u32 a;
    asm("{ .reg .u64 t; cvta.to.shared.u64 t, %1; cvt.u32.u64 %0, t; }"
        : "=r"(a) : "l"(p));
    return a;
}

__device__ __forceinline__ void cp_async16(u32 dst, const void* src, int sz)
{
    asm volatile("cp.async.cg.shared.global [%0], [%1], 16, %2;"
        :: "r"(dst), "l"(src), "r"(sz));
}
#define CP_COMMIT() asm volatile("cp.async.commit_group;" ::: "memory")
#define CP_WAIT1()  asm volatile("cp.async.wait_group 1;" ::: "memory")
#define CP_WAIT0()  asm volatile("cp.async.wait_group 0;" ::: "memory")

__device__ __forceinline__ void ldsm4(u32 addr, u32& r0, u32& r1, u32& r2, u32& r3)
{
    asm volatile("ldmatrix.sync.aligned.m8n8.x4.shared.b16 {%0,%1,%2,%3}, [%4];"
        : "=r"(r0), "=r"(r1), "=r"(r2), "=r"(r3) : "r"(addr));
}
__device__ __forceinline__ void ldsm4t(u32 addr, u32& r0, u32& r1, u32& r2, u32& r3)
{
    asm volatile("ldmatrix.sync.aligned.m8n8.x4.trans.shared.b16 {%0,%1,%2,%3}, [%4];"
        : "=r"(r0), "=r"(r1), "=r"(r2), "=r"(r3) : "r"(addr));
}

__device__ __forceinline__ void mma_bf16(float* d, const u32* a, u32 b0, u32 b1)
{
    asm volatile(
        "mma.sync.aligned.m16n8k16.row.col.f32.bf16.bf16.f32 "
        "{%0,%1,%2,%3},{%4,%5,%6,%7},{%8,%9},{%0,%1,%2,%3};"
        : "+f"(d[0]), "+f"(d[1]), "+f"(d[2]), "+f"(d[3])
        : "r"(a[0]), "r"(a[1]), "r"(a[2]), "r"(a[3]), "r"(b0), "r"(b1));
}
__device__ __forceinline__ void mma_f16(float* d, const u32* a, u32 b0, u32 b1)
{
    asm volatile(
        "mma.sync.aligned.m16n8k16.row.col.f32.f16.f16.f32 "
        "{%0,%1,%2,%3},{%4,%5,%6,%7},{%8,%9},{%0,%1,%2,%3};"
        : "+f"(d[0]), "+f"(d[1]), "+f"(d[2]), "+f"(d[3])
        : "r"(a[0]), "r"(a[1]), "r"(a[2]), "r"(a[3]), "r"(b0), "r"(b1));
}

// pack two fp32 into bf16x2 word: first arg -> lower halfword
__device__ __forceinline__ u32 pack_bf(float lo, float hi)
{
    u32 r;
    asm("cvt.rn.bf16x2.f32 %0, %1, %2;" : "=r"(r) : "f"(hi), "f"(lo));
    return r;
}
__device__ __forceinline__ u32 pack_h2(float lo, float hi)
{
    __half2 h = __floats2half2_rn(lo, hi);
    return *(u32*)&h;
}

__device__ __forceinline__ float bf_round(float v)
{
    return __bfloat162float(__float2bfloat16(v));
}

__device__ __forceinline__ void split_write(bf16* h, bf16* l, size_t idx, float v)
{
    bf16 hh = __float2bfloat16(v);
    h[idx] = hh;
    l[idx] = __float2bfloat16(v - __bfloat162float(hh));
}

__device__ __forceinline__ void split_store2(bf16* h, bf16* l, size_t idx,
                                             float v0, float v1)
{
    float h0 = bf_round(v0), h1 = bf_round(v1);
    *(u32*)(h + idx) = pack_bf(h0, h1);
    *(u32*)(l + idx) = pack_bf(v0 - h0, v1 - h1);
}

// ----------------------------------------------------------------------------
// Weight conversion: one contiguous segment -> bf16 hi/lo (n8 8-elem units)
// ----------------------------------------------------------------------------
__global__ void cvt_seg_kernel(const float* __restrict__ src,
                               bf16* __restrict__ h, bf16* __restrict__ l,
                               long long n8)
{
    for (long long i = (long long)blockIdx.x * 256 + threadIdx.x; i < n8;
         i += (long long)gridDim.x * 256) {
        const float4* xp = (const float4*)src + 2 * i;
        float4 a = xp[0], b = xp[1];
        float h0 = bf_round(a.x), h1 = bf_round(a.y),
              h2 = bf_round(a.z), h3 = bf_round(a.w),
              h4 = bf_round(b.x), h5 = bf_round(b.y),
              h6 = bf_round(b.z), h7 = bf_round(b.w);
        uint4 H, L;
        H.x = pack_bf(h0, h1); H.y = pack_bf(h2, h3);
        H.z = pack_bf(h4, h5); H.w = pack_bf(h6, h7);
        L.x = pack_bf(a.x - h0, a.y - h1); L.y = pack_bf(a.z - h2, a.w - h3);
        L.z = pack_bf(b.x - h4, b.y - h5); L.w = pack_bf(b.z - h6, b.w - h7);
        ((uint4*)h)[i] = H;
        ((uint4*)l)[i] = L;
    }
}

// cls_w2: [NE,100] -> [NE,112] zero-padded FP16 single (hi only; 1-term cls2)
__global__ void cvt_pad_kernel(const float* __restrict__ x,
                               bf16* __restrict__ h)
{
    int total = NE * 28;
    for (int i = blockIdx.x * 256 + threadIdx.x; i < total; i += gridDim.x * 256) {
        int r = i / 28, c4 = (i - r * 28) * 4;
        u32 ha = 0, hb = 0;
        if (c4 < 100) {
            float4 v = *(const float4*)(x + (size_t)r * 100 + c4);
            ha = pack_h2(v.x, v.y); hb = pack_h2(v.z, v.w);
        }
        size_t o = (size_t)r * KPAD + c4;
        *(uint2*)(h + o) = make_uint2(ha, hb);
    }
}

// ----------------------------------------------------------------------------
// Mention pooling (pos/mask int32), inline attention logits.
// ----------------------------------------------------------------------------
__global__ __launch_bounds__(256)
void pool_kernel(const float* __restrict__ lhs,
                 const int* __restrict__ pos,
                 const int* __restrict__ mask,
                 const float* __restrict__ aw,
                 float* __restrict__ x,
                 bf16* __restrict__ xh, bf16* __restrict__ xl)
{
    int bm = blockIdx.x;
    int b = bm >> 7;
    int t = threadIdx.x;
    __shared__ float dots[LL];
    __shared__ float ws[LL];
    __shared__ int s_nv;

    {
        int l = t >> 3, sub = t & 7;
        const float* row = lhs + ((size_t)b * SS + l) * DD;
        float p = 0.f;
        for (int j = sub; j < DD; j += 8) p += row[j] * aw[j];
        #pragma unroll
        for (int o = 4; o; o >>= 1) p += __shfl_xor_sync(~0u, p, o);
        if (sub == 0) dots[l] = p;
    }
    __syncthreads();

    if (t < 32) {
        int p = pos[(size_t)bm * LL + t];
        unsigned bits = __ballot_sync(0xffffffffu, p != -1);
        int nv;
        if (mask[bm] == 0) nv = 0;
        else if (~bits == 0u) nv = 32;
        else nv = __ffs(~bits) - 1;
        float logit = (t < nv) ? dots[t] : 0.f;
        float mx = logit;
        #pragma unroll
        for (int o = 16; o; o >>= 1) mx = fmaxf(mx, __shfl_xor_sync(~0u, mx, o));
        float e = expf(logit - mx);
        float s = e;
        #pragma unroll
        for (int o = 16; o; o >>= 1) s += __shfl_xor_sync(~0u, s, o);
        ws[t] = e / s;
        if (t == 0) s_nv = nv;
    }
    __syncthreads();
    int nv = s_nv;
    for (int d = t; d < DD; d += 256) {
        float acc = 0.f;
        for (int l = 0; l < nv; l++)
            acc += ws[l] * lhs[((size_t)b * SS + l) * DD + d];
        size_t idx = (size_t)bm * DD + d;
        x[idx] = acc;
        split_write(xh, xl, idx, acc);
    }
}

// ----------------------------------------------------------------------------
// Tensor-core split NT GEMM. AXSW=1 swaps blockIdx.x/y roles so that the
// M-dimension is fastest-varying (adjacent CTAs share B tiles -> L2 reuse
// under heavy C-store eviction pressure; used for cls2).
// ----------------------------------------------------------------------------
template<int TM, int TN, int RELU, int SPLIT, int PREC, int OCC, int AXSW>
__global__ __launch_bounds__(256, OCC)
void gemm_tc(const bf16* __restrict__ Ah, const bf16* __restrict__ Al,
             const bf16* __restrict__ Bh, const bf16* __restrict__ Bl,
             const float* __restrict__ bias,
             float* __restrict__ C, bf16* __restrict__ Ch, bf16* __restrict__ Cl,
             int M, int N, int lda, int ldb, int Klen, int ldout, int padN)
{
    constexpr int MI  = TM / 64;
    constexpr int NJW = TN / 16;
    constexpr int NA  = (PREC == 0) ? 2 : 1;
    constexpr int NB  = (PREC == 2) ? 1 : 2;
    constexpr int ASZ = TM * 64;
    constexpr int BSZ = TN * 64;
    constexpr int BUF = NA * ASZ + NB * BSZ;

    extern __shared__ char smem[];
    const u32 base = smem_u32(smem);
    const int t = threadIdx.x, lane = t & 31, warp = t >> 5;
    const int mBase = (AXSW ? blockIdx.x : blockIdx.y) * TM;
    const int nBase = (AXSW ? blockIdx.y : blockIdx.x) * TN;
    const int kOff = blockIdx.z * Klen;
    const int wm = (warp >> 1) * (TM / 4), wn = (warp & 1) * (TN / 2);
    const int ar0 = wm + (lane & 15);
    const int ahi = lane >> 4;
    const int br0 = wn + (lane & 7) + ((lane >> 4) << 3);
    const int bhi = (lane >> 3) & 1;

    float acc[MI][NJW][4];
    #pragma unroll
    for (int mi = 0; mi < MI; mi++)
        #pragma unroll
        for (int nj = 0; nj < NJW; nj++)
            #pragma unroll
            for (int r = 0; r < 4; r++) acc[mi][nj][r] = 0.f;

    const int S = (Klen + 31) / 32;

    auto loadSlab = [&](int s) {
        const int k0 = s * 32;
        const u32 bb = base + (s % 3) * BUF;
        #pragma unroll
        for (int p = 0; p < TM / 64; p++) {
            int c = p * 256 + t, row = c >> 2, ch = c & 3;
            int kk = k0 + ch * 8;
            int avail = Klen - kk;
            int sz = (avail >= 8) ? 16 : (avail > 0 ? avail * 2 : 0);
            u32 off = row * 64 + ((u32)(ch ^ ((row >> 1) & 3)) << 4);
            cp_async16(bb + off, Ah + (size_t)(mBase + row) * lda + kOff + kk, sz);
            if (PREC == 0)
                cp_async16(bb + ASZ + off, Al + (size_t)(mBase + row) * lda + kOff + kk, sz);
        }
        #pragma unroll
        for (int p = 0; p < TN / 64; p++) {
            int c = p * 256 + t, row = c >> 2, ch = c & 3;
            int kk = k0 + ch * 8;
            int avail = Klen - kk;
            int sz = (avail >= 8) ? 16 : (avail > 0 ? avail * 2 : 0);
            if (nBase + row >= N) sz = 0;
            u32 off = row * 64 + ((u32)(ch ^ ((row >> 1) & 3)) << 4);
            cp_async16(bb + NA * ASZ + off, Bh + (size_t)(nBase + row) * ldb + kOff + kk, sz);
            if (PREC < 2)
                cp_async16(bb + NA * ASZ + BSZ + off, Bl + (size_t)(nBase + row) * ldb + kOff + kk, sz);
        }
    };

    loadSlab(0);
    CP_COMMIT();
    if (S > 1) loadSlab(1);
    CP_COMMIT();

    for (int s = 0; s < S; s++) {
        CP_WAIT1();
        __syncthreads();
        if (s + 2 < S) loadSlab(s + 2);
        CP_COMMIT();

        const u32 bb = base + (s % 3) * BUF;
        const u32 aB0 = bb, aB1 = bb + ASZ;
        const u32 bB0 = bb + NA * ASZ, bB1 = bb + NA * ASZ + BSZ;

        #pragma unroll
        for (int ks = 0; ks < 2; ks++) {
            u32 ahf[MI][4], alf[MI][4];
            #pragma unroll
            for (int mi = 0; mi < MI; mi++) {
                int row = ar0 + mi * 16;
                u32 off = row * 64 + ((u32)((ks * 2 + ahi) ^ ((row >> 1) & 3)) << 4);
                ldsm4(aB0 + off, ahf[mi][0], ahf[mi][1], ahf[mi][2], ahf[mi][3]);
                if (PREC == 0)
                    ldsm4(aB1 + off, alf[mi][0], alf[mi][1], alf[mi][2], alf[mi][3]);
            }
            #pragma unroll
            for (int j = 0; j < NJW / 2; j++) {
                int row = br0 + j * 16;
                u32 off = row * 64 + ((u32)((ks * 2 + bhi) ^ ((row >> 1) & 3)) << 4);
                u32 b0, b1, b2, b3, l0, l1, l2, l3;
                ldsm4(bB0 + off, b0, b1, b2, b3);
                if (PREC < 2) ldsm4(bB1 + off, l0, l1, l2, l3);
                if (PREC == 0) {
                    #pragma unroll
                    for (int mi = 0; mi < MI; mi++) {
                        mma_bf16(acc[mi][2 * j],     ahf[mi], b0, b1);
                        mma_bf16(acc[mi][2 * j + 1], ahf[mi], b2, b3);
                    }
                    #pragma unroll
                    for (int mi = 0; mi < MI; mi++) {
                        mma_bf16(acc[mi][2 * j],     ahf[mi], l0, l1);
                        mma_bf16(acc[mi][2 * j + 1], ahf[mi], l2, l3);
                    }
                    #pragma unroll
                    for (int mi = 0; mi < MI; mi++) {
                        mma_bf16(acc[mi][2 * j],     alf[mi], b0, b1);
                        mma_bf16(acc[mi][2 * j + 1], alf[mi], b2, b3);
                    }
                } else if (PREC == 1) {
                    #pragma unroll
                    for (int mi = 0; mi < MI; mi++) {
                        mma_f16(acc[mi][2 * j],     ahf[mi], b0, b1);
                        mma_f16(acc[mi][2 * j + 1], ahf[mi], b2, b3);
                    }
                    #pragma unroll
                    for (int mi = 0; mi < MI; mi++) {
                        mma_f16(acc[mi][2 * j],     ahf[mi], l0, l1);
                        mma_f16(acc[mi][2 * j + 1], ahf[mi], l2, l3);
                    }
                } else {
                    #pragma unroll
                    for (int mi = 0; mi < MI; mi++) {
                        mma_f16(acc[mi][2 * j],     ahf[mi], b0, b1);
                        mma_f16(acc[mi][2 * j + 1], ahf[mi], b2, b3);
                    }
                }
            }
        }
    }

    // epilogue
    float* Cz = C + (size_t)blockIdx.z * M * ldout;
    const int g = lane >> 2, tg = lane & 3;
    #pragma unroll
    for (int mi = 0; mi < MI; mi++) {
        int row0 = mBase + wm + mi * 16 + g;
        #pragma unroll
        for (int nj = 0; nj < NJW; nj++) {
            int col0 = nBase + wn + nj * 8 + 2 * tg;
            if (col0 < padN) {
                #pragma unroll
                for (int rr = 0; rr < 2; rr++) {
                    int row = row0 + rr * 8;
                    float v0 = 0.f, v1 = 0.f;
                    if (col0 < N) {
                        v0 = acc[mi][nj][rr * 2 + 0] + (bias ? bias[col0] : 0.f);
                        v1 = acc[mi][nj][rr * 2 + 1] + (bias ? bias[col0 + 1] : 0.f);
                        if (RELU) { v0 = fmaxf(v0, 0.f); v1 = fmaxf(v1, 0.f); }
                    }
                    size_t idx = (size_t)row * ldout + col0;
                    if (SPLIT == 1)      split_store2(Ch, Cl, idx, v0, v1);
                    else if (SPLIT == 2) *(u32*)(Ch + idx) = pack_h2(v0, v1);
                    else                 *(float2*)(Cz + idx) = make_float2(v0, v1);
                }
            }
        }
    }
}

// ----------------------------------------------------------------------------
// Fused attention, Q-split: one CTA per (b,h,half). 4 warps x 16 Q-rows = 64.
// 128 threads, 2 CTAs/SM. Full K/V tiles; Q covers rows [half*64, half*64+64).
// ----------------------------------------------------------------------------
#define SMEMATT (2 * 8192 + 4 * 16384)     // 81920

__global__ __launch_bounds__(128, 2)
void attn_fused(const bf16* __restrict__ qkvh, const bf16* __restrict__ qkvl,
                bf16* __restrict__ aoh, bf16* __restrict__ aol)
{
    extern __shared__ char smem[];
    const u32 base = smem_u32(smem);
    const int t = threadIdx.x, lane = t & 31, warp = t >> 5;
    const int bh2 = blockIdx.x, bh = bh2 >> 1, half = bh2 & 1;
    const int b = bh / HH, h = bh % HH;
    const size_t rowBase = (size_t)b * MM;
    const int qOff = half * 64;
    const int g = lane >> 2, tg = lane & 3;

    const u32 sQh = base, sQl = base + 8192;
    const u32 sKh = base + 16384, sKl = base + 32768;
    const u32 sVh = base + 49152, sVl = base + 65536;

    #pragma unroll
    for (int m = 0; m < 2; m++) {
        const bf16* src = m ? qkvl : qkvh;
        u32 dst = m ? sQl : sQh;
        #pragma unroll
        for (int p = 0; p < 4; p++) {
            int c = p * 128 + t;
            int row = c >> 3, ch = c & 7;
            u32 off = row * 128 + ((u32)(ch ^ (row & 7)) << 4);
            cp_async16(dst + off,
                       src + (rowBase + qOff + row) * (3 * DD) + h * HD + ch * 8, 16);
        }
    }
    #pragma unroll
    for (int m = 0; m < 4; m++) {
        const bf16* src = (m & 1) ? qkvl : qkvh;
        int colOff = (1 + (m >> 1)) * DD + h * HD;   // K then V
        u32 dst = (m == 0) ? sKh : (m == 1) ? sKl : (m == 2) ? sVh : sVl;
        #pragma unroll
        for (int p = 0; p < 8; p++) {
            int c = p * 128 + t;
            int row = c >> 3, ch = c & 7;
            u32 off = row * 128 + ((u32)(ch ^ (row & 7)) << 4);
            cp_async16(dst + off,
                       src + (rowBase + row) * (3 * DD) + colOff + ch * 8, 16);
        }
    }
    CP_COMMIT(); CP_WAIT0();
    __syncthreads();

    const int m0 = warp * 16;

    float acc[16][4];
    #pragma unroll
    for (int nj = 0; nj < 16; nj++)
        #pragma unroll
        for (int r = 0; r < 4; r++) acc[nj][r] = 0.f;

    const int tile = lane >> 3, wr = lane & 7;
    #pragma unroll
    for (int kk = 0; kk < 4; kk++) {
        u32 qh4[4], ql4[4];
        {
            int row = m0 + wr + (tile & 1) * 8;
            int ch = kk * 2 + (tile >> 1);
            u32 off = row * 128 + ((u32)(ch ^ (row & 7)) << 4);
            ldsm4(sQh + off, qh4[0], qh4[1], qh4[2], qh4[3]);
            ldsm4(sQl + off, ql4[0], ql4[1], ql4[2], ql4[3]);
        }
        #pragma unroll
        for (int nj2 = 0; nj2 < 8; nj2++) {
            int row = nj2 * 16 + wr + (tile >> 1) * 8;
            int ch = kk * 2 + (tile & 1);
            u32 off = row * 128 + ((u32)(ch ^ (row & 7)) << 4);
            u32 b0, b1, b2, b3, l0, l1, l2, l3;
            ldsm4(sKh + off, b0, b1, b2, b3);
            ldsm4(sKl + off, l0, l1, l2, l3);
            mma_bf16(acc[2 * nj2],     qh4, b0, b1);
            mma_bf16(acc[2 * nj2 + 1], qh4, b2, b3);
            mma_bf16(acc[2 * nj2],     qh4, l0, l1);
            mma_bf16(acc[2 * nj2 + 1], qh4, l2, l3);
            mma_bf16(acc[2 * nj2],     ql4, b0, b1);
            mma_bf16(acc[2 * nj2 + 1], ql4, b2, b3);
        }
    }

    {
        float mx0 = -1e30f, mx1 = -1e30f;
        #pragma unroll
        for (int nj = 0; nj < 16; nj++) {
            acc[nj][0] *= 0.125f; acc[nj][1] *= 0.125f;
            acc[nj][2] *= 0.125f; acc[nj][3] *= 0.125f;
            mx0 = fmaxf(mx0, fmaxf(acc[nj][0], acc[nj][1]));
            mx1 = fmaxf(mx1, fmaxf(acc[nj][2], acc[nj][3]));
        }
        mx0 = fmaxf(mx0, __shfl_xor_sync(~0u, mx0, 1));
        mx0 = fmaxf(mx0, __shfl_xor_sync(~0u, mx0, 2));
        mx1 = fmaxf(mx1, __shfl_xor_sync(~0u, mx1, 1));
        mx1 = fmaxf(mx1, __shfl_xor_sync(~0u, mx1, 2));
        float s0 = 0.f, s1 = 0.f;
        #pragma unroll
        for (int nj = 0; nj < 16; nj++) {
            acc[nj][0] = expf(acc[nj][0] - mx0);
            acc[nj][1] = expf(acc[nj][1] - mx0);
            acc[nj][2] = expf(acc[nj][2] - mx1);
            acc[nj][3] = expf(acc[nj][3] - mx1);
            s0 += acc[nj][0] + acc[nj][1];
            s1 += acc[nj][2] + acc[nj][3];
        }
        s0 += __shfl_xor_sync(~0u, s0, 1);
        s0 += __shfl_xor_sync(~0u, s0, 2);
        s1 += __shfl_xor_sync(~0u, s1, 1);
        s1 += __shfl_xor_sync(~0u, s1, 2);
        float i0 = 1.f / s0, i1 = 1.f / s1;
        #pragma unroll
        for (int nj = 0; nj < 16; nj++) {
            acc[nj][0] *= i0; acc[nj][1] *= i0;
            acc[nj][2] *= i1; acc[nj][3] *= i1;
        }
    }

    float o[8][4];
    #pragma unroll
    for (int nj = 0; nj < 8; nj++)
        #pragma unroll
        for (int r = 0; r < 4; r++) o[nj][r] = 0.f;

    #pragma unroll
    for (int j = 0; j < 8; j++) {
        u32 pa_h[4], pa_l[4];
        #pragma unroll
        for (int q = 0; q < 2; q++) {
            float p0 = acc[2 * j + q][0], p1 = acc[2 * j + q][1];
            float p2 = acc[2 * j + q][2], p3 = acc[2 * j + q][3];
            float h0 = bf_round(p0), h1 = bf_round(p1);
            float h2 = bf_round(p2), h3 = bf_round(p3);
            pa_h[0 + 2 * q] = pack_bf(h0, h1);
            pa_h[1 + 2 * q] = pack_bf(h2, h3);
            pa_l[0 + 2 * q] = pack_bf(p0 - h0, p1 - h1);
            pa_l[1 + 2 * q] = pack_bf(p2 - h2, p3 - h3);
        }
        #pragma unroll
        for (int c2 = 0; c2 < 4; c2++) {
            int row = j * 16 + wr + (tile & 1) * 8;
            int ch = 2 * c2 + (tile >> 1);
            u32 off = row * 128 + ((u32)(ch ^ (row & 7)) << 4);
            u32 v0, v1, v2, v3, w0, w1, w2, w3;
            ldsm4t(sVh + off, v0, v1, v2, v3);
            ldsm4t(sVl + off, w0, w1, w2, w3);
            mma_bf16(o[2 * c2],     pa_h, v0, v1);
            mma_bf16(o[2 * c2 + 1], pa_h, v2, v3);
            mma_bf16(o[2 * c2],     pa_h, w0, w1);
            mma_bf16(o[2 * c2 + 1], pa_h, w2, w3);
            mma_bf16(o[2 * c2],     pa_l, v0, v1);
            mma_bf16(o[2 * c2 + 1], pa_l, v2, v3);
        }
    }

    {
        size_t gr = rowBase + qOff + m0 + g;
        #pragma unroll
        for (int nj = 0; nj < 8; nj++) {
            int col = h * HD + nj * 8 + 2 * tg;
            split_store2(aoh, aol, gr * DD + col, o[nj][0], o[nj][1]);
            split_store2(aoh, aol, (gr + 8) * DD + col, o[nj][2], o[nj][3]);
        }
    }
}

// ----------------------------------------------------------------------------
// x = LayerNorm(x + d0 + d1 + bias) * w + b; writes bf16 split of x
// ----------------------------------------------------------------------------
__global__ __launch_bounds__(256)
void add_ln_kernel(float* __restrict__ x,
                   const float* __restrict__ d0p, const float* __restrict__ d1p,
                   const float* __restrict__ bias,
                   const float* __restrict__ w, const float* __restrict__ b,
                   bf16* __restrict__ xh, bf16* __restrict__ xl)
{
    int row = blockIdx.x, t = threadIdx.x;
    float* xp = x + (size_t)row * DD;
    const float* a0 = d0p + (size_t)row * DD;
    const float* a1 = d1p + (size_t)row * DD;
    float v0 = xp[t]       + a0[t]       + a1[t]       + bias[t];
    float v1 = xp[t + 256] + a0[t + 256] + a1[t + 256] + bias[t + 256];
    float v2 = xp[t + 512] + a0[t + 512] + a1[t + 512] + bias[t + 512];
    float s = v0 + v1 + v2;
    __shared__ float red[8];
    #pragma unroll
    for (int o = 16; o; o >>= 1) s += __shfl_xor_sync(~0u, s, o);
    if ((t & 31) == 0) red[t >> 5] = s;
    __syncthreads();
    float tot = red[0] + red[1] + red[2] + red[3] + red[4] + red[5] + red[6] + red[7];
    float mu = tot * (1.f / 768.f);
    float d0 = v0 - mu, d1 = v1 - mu, d2 = v2 - mu;
    float q = d0 * d0 + d1 * d1 + d2 * d2;
    #pragma unroll
    for (int o = 16; o; o >>= 1) q += __shfl_xor_sync(~0u, q, o);
    __syncthreads();
    if ((t & 31) == 0) red[t >> 5] = q;
    __syncthreads();
    float qt = red[0] + red[1] + red[2] + red[3] + red[4] + red[5] + red[6] + red[7];
    float inv = rsqrtf(qt * (1.f / 768.f) + 1e-5f);
    float o0 = d0 * inv * w[t]       + b[t];
    float o1 = d1 * inv * w[t + 256] + b[t + 256];
    float o2 = d2 * inv * w[t + 512] + b[t + 512];
    size_t rb = (size_t)row * DD;
    xp[t] = o0;       split_write(xh, xl, rb + t,       o0);
    xp[t + 256] = o1; split_write(xh, xl, rb + t + 256, o1);
    xp[t + 512] = o2; split_write(xh, xl, rb + t + 512, o2);
}

// ----------------------------------------------------------------------------
// Host-side launch
// ----------------------------------------------------------------------------
template<typename T>
static T* sym(const void* s)
{
    void* p = nullptr;
    cudaGetSymbolAddress(&p, s);
    return (T*)p;
}

#define SMEM_G(TM, TN, NA, NB) (3 * ((NA) * (TM) * 64 + (NB) * (TN) * 64))

extern "C" void kernel_launch(void* const* d_in, const int* in_sizes, int n_in,
                              void* d_out, int out_size)
{
    static const long long want[20] = {
        6291456LL, 65536LL, 2048LL, 768LL, 1LL,
        7077888LL, 9216LL, 2359296LL, 3072LL, 3072LL, 3072LL,
        9437184LL, 12288LL, 9437184LL, 3072LL, 3072LL, 3072LL,
        76800LL, 5000000LL, 50000LL
    };
    const void* slot[20];
    bool used[64];
    for (int i = 0; i < 20; i++) slot[i] = nullptr;
    for (int i = 0; i < n_in && i < 64; i++) used[i] = false;
    for (int w = 0; w < 20; w++) {
        for (int i = 0; i < n_in && i < 64; i++) {
            if (!used[i] && (long long)in_sizes[i] == want[w]) {
                slot[w] = d_in[i];
                used[i] = true;
                break;
            }
        }
    }
    if (!slot[0]) {
        for (int w = 0; w < 20 && w < n_in; w++) slot[w] = d_in[w];
    }

    const float* lhs    = (const float*)slot[0];
    const int*   pos    = (const int*)slot[1];
    const int*   mask   = (const int*)slot[2];
    const float* attn_w = (const float*)slot[3];
    const float* qkv_w  = (const float*)slot[5];
    const float* qkv_b  = (const float*)slot[6];
    const float* out_w  = (const float*)slot[7];
    const float* out_b  = (const float*)slot[8];
    const float* ln1_w  = (const float*)slot[9];
    const float* ln1_b  = (const float*)slot[10];
    const float* ff1_w  = (const float*)slot[11];
    const float* ff1_b  = (const float*)slot[12];
    const float* ff2_w  = (const float*)slot[13];
    const float* ff2_b  = (const float*)slot[14];
    const float* ln2_w  = (const float*)slot[15];
    const float* ln2_b  = (const float*)slot[16];
    const float* cls_w1 = (const float*)slot[17];
    const float* cls_w2 = (const float*)slot[18];
    const float* cls_b2 = (const float*)slot[19];
    float* out = (float*)d_out;

    float* x   = sym<float>(g_x);
    float* tmp = sym<float>(g_tmp);
    bf16*  wh  = sym<bf16>(g_wh);
    bf16*  wl  = sym<bf16>(g_wl);
    bf16*  ah  = sym<bf16>(g_ah);
    bf16*  al  = sym<bf16>(g_al);
    bf16*  bh2 = sym<bf16>(g_bh);
    bf16*  bl2 = sym<bf16>(g_bl);

    cudaFuncSetAttribute(gemm_tc<128, 128, 0, 1, 0, 2, 0>, cudaFuncAttributeMaxDynamicSharedMemorySize, SMEM_G(128, 128, 2, 2));
    cudaFuncSetAttribute(gemm_tc<128, 64, 0, 0, 0, 3, 0>,  cudaFuncAttributeMaxDynamicSharedMemorySize, SMEM_G(128, 64, 2, 2));
    cudaFuncSetAttribute(gemm_tc<128, 64, 1, 1, 0, 3, 0>,  cudaFuncAttributeMaxDynamicSharedMemorySize, SMEM_G(128, 64, 2, 2));
    cudaFuncSetAttribute(gemm_tc<128, 64, 0, 2, 0, 3, 0>,  cudaFuncAttributeMaxDynamicSharedMemorySize, SMEM_G(128, 64, 2, 2));
    cudaFuncSetAttribute(gemm_tc<128, 128, 0, 0, 2, 2, 1>, cudaFuncAttributeMaxDynamicSharedMemorySize, SMEM_G(128, 128, 1, 1));
    cudaFuncSetAttribute(attn_fused, cudaFuncAttributeMaxDynamicSharedMemorySize, SMEMATT);

    // --- prologue pipeline ---
    cudaStream_t s2;
    cudaStreamCreateWithFlags(&s2, cudaStreamNonBlocking);
    cudaEvent_t eFork, ePool, eJoin;
    cudaEventCreateWithFlags(&eFork, cudaEventDisableTiming);
    cudaEventCreateWithFlags(&ePool, cudaEventDisableTiming);
    cudaEventCreateWithFlags(&eJoin, cudaEventDisableTiming);

    cudaEventRecord(eFork, 0);
    cudaStreamWaitEvent(s2, eFork, 0);
    pool_kernel<<<ROWS, 256, 0, s2>>>(lhs, pos, mask, attn_w, x, ah, al);
    cudaEventRecord(ePool, s2);
    cvt_seg_kernel<<<2048, 256, 0, s2>>>(out_w,  wh + OW_OUT,  wl + OW_OUT,  294912);
    cvt_seg_kernel<<<4096, 256, 0, s2>>>(ff1_w,  wh + OW_FF1,  wl + OW_FF1,  1179648);
    cvt_seg_kernel<<<4096, 256, 0, s2>>>(ff2_w,  wh + OW_FF2,  wl + OW_FF2,  1179648);
    cvt_seg_kernel<<<64,   256, 0, s2>>>(cls_w1, wh + OW_CLS1, wl + OW_CLS1, 9600);
    cvt_pad_kernel<<<2736, 256, 0, s2>>>(cls_w2, wh + OW_CLS2);
    cudaEventRecord(eJoin, s2);

    cvt_seg_kernel<<<3456, 256>>>(qkv_w, wh + OW_QKV, wl + OW_QKV, 884736);
    cudaStreamWaitEvent(0, ePool, 0);

    // --- transformer layers ---
    for (int i = 0; i < NL; i++) {
        gemm_tc<128, 128, 0, 1, 0, 2, 0><<<dim3(18, 16, 1), 256, SMEM_G(128, 128, 2, 2)>>>(
            ah, al, wh + OW_QKV + (size_t)i * 3 * DD * DD,
            wl + OW_QKV + (size_t)i * 3 * DD * DD,
            qkv_b + (size_t)i * 3 * DD, nullptr, bh2, bl2,
            ROWS, 3 * DD, DD, DD, DD, 3 * DD, 3 * DD);
        attn_fused<<<BB * HH * 2, 128, SMEMATT>>>(bh2, bl2, ah, al);
        if (i == 0) cudaStreamWaitEvent(0, eJoin, 0);
        gemm_tc<128, 64, 0, 0, 0, 3, 0><<<dim3(12, 16, 2), 256, SMEM_G(128, 64, 2, 2)>>>(
            ah, al, wh + OW_OUT + (size_t)i * DD * DD,
            wl + OW_OUT + (size_t)i * DD * DD,
            nullptr, tmp, nullptr, nullptr,
            ROWS, DD, DD, DD, DD / 2, DD, DD);
        add_ln_kernel<<<ROWS, 256>>>(x, tmp, tmp + (size_t)ROWS * DD,
                                     out_b + (size_t)i * DD,
                                     ln1_w + (size_t)i * DD, ln1_b + (size_t)i * DD,
                                     ah, al);
        gemm_tc<128, 64, 1, 1, 0, 3, 0><<<dim3(48, 16, 1), 256, SMEM_G(128, 64, 2, 2)>>>(
            ah, al, wh + OW_FF1 + (size_t)i * DFF * DD,
            wl + OW_FF1 + (size_t)i * DFF * DD,
            ff1_b + (size_t)i * DFF, nullptr, bh2, bl2,
            ROWS, DFF, DD, DD, DD, DFF, DFF);
        gemm_tc<128, 64, 0, 0, 0, 3, 0><<<dim3(12, 16, 2), 256, SMEM_G(128, 64, 2, 2)>>>(
            bh2, bl2, wh + OW_FF2 + (size_t)i * DD * DFF,
            wl + OW_FF2 + (size_t)i * DD * DFF,
            nullptr, tmp, nullptr, nullptr,
            ROWS, DD, DFF, DFF, DFF / 2, DD, DD);
        add_ln_kernel<<<ROWS, 256>>>(x, tmp, tmp + (size_t)ROWS * DD,
                                     ff2_b + (size_t)i * DD,
                                     ln2_w + (size_t)i * DD, ln2_b + (size_t)i * DD,
                                     ah, al);
    }

    // --- classifier head ---
    gemm_tc<128, 64, 0, 2, 0, 3, 0><<<dim3(2, 16, 1), 256, SMEM_G(128, 64, 2, 2)>>>(
        ah, al, wh + OW_CLS1, wl + OW_CLS1, nullptr,
        nullptr, bh2, nullptr, ROWS, 100, DD, DD, DD, KPAD, KPAD);
    // cls2: AXSW=1 -> grid (M-tiles fast, N-tiles slow) for B-tile L2 reuse
    gemm_tc<128, 128, 0, 0, 2, 2, 1><<<dim3(16, (NE + 127) / 128, 1), 256, SMEM_G(128, 128, 1, 1)>>>(
        bh2, nullptr, wh + OW_CLS2, nullptr, cls_b2,
        out, nullptr, nullptr, ROWS, NE, KPAD, KPAD, KPAD, NE, NE);
}

// round 16
// speedup vs baseline: 1.0208x; 1.0208x over previous
#include <cuda_runtime.h>
#include <cuda_bf16.h>
#include <cuda_fp16.h>
#include <math.h>
#include <cstdint>

// ----------------------------------------------------------------------------
// Problem constants
// ----------------------------------------------------------------------------
#define BB   16
#define MM   128
#define LL   32
#define SS   512
#define DD   768
#define HH   12
#define HD   64
#define DFF  3072
#define NL   4
#define NE   50000
#define ROWS (BB*MM)          // 2048
#define KPAD 112              // padded K for classifier stage 2

typedef unsigned long long ull;
typedef unsigned int u32;
typedef __nv_bfloat16 bf16;

// weight scratch offsets (elements)
#define OW_QKV  0ULL
#define OW_OUT  7077888ULL
#define OW_FF1  9437184ULL
#define OW_FF2  18874368ULL
#define OW_CLS1 28311552ULL
#define OW_CLS2 28388352ULL
#define NW_TOT  (28388352ULL + 50000ULL*KPAD)

// ----------------------------------------------------------------------------
// Device scratch (static allocation — no cudaMalloc allowed)
// ----------------------------------------------------------------------------
__device__ float g_x [ROWS*DD];
__device__ float g_tmp[ROWS*DFF];            // split-K partials (2 x ROWS*DD)
__device__ __align__(256) bf16 g_wh[NW_TOT];
__device__ __align__(256) bf16 g_wl[NW_TOT];
__device__ __align__(256) bf16 g_ah[ROWS*DFF];
__device__ __align__(256) bf16 g_al[ROWS*DFF];
__device__ __align__(256) bf16 g_bh[ROWS*DFF];
__device__ __align__(256) bf16 g_bl[ROWS*DFF];

// ----------------------------------------------------------------------------
// PTX helpers
// ----------------------------------------------------------------------------
__device__ __forceinline__ u32 smem_u32(const void* p)
{
    u32 a;
    asm("{ .reg .u64 t; cvta.to.shared.u64 t, %1; cvt.u32.u64 %0, t; }"
        : "=r"(a) : "l"(p));
    return a;
}

__device__ __forceinline__ void cp_async16(u32 dst, const void* src, int sz)
{
    asm volatile("cp.async.cg.shared.global [%0], [%1], 16, %2;"
        :: "r"(dst), "l"(src), "r"(sz));
}
#define CP_COMMIT() asm volatile("cp.async.commit_group;" ::: "memory")
#define CP_WAIT1()  asm volatile("cp.async.wait_group 1;" ::: "memory")
#define CP_WAIT0()  asm volatile("cp.async.wait_group 0;" ::: "memory")

__device__ __forceinline__ void ldsm4(u32 addr, u32& r0, u32& r1, u32& r2, u32& r3)
{
    asm volatile("ldmatrix.sync.aligned.m8n8.x4.shared.b16 {%0,%1,%2,%3}, [%4];"
        : "=r"(r0), "=r"(r1), "=r"(r2), "=r"(r3) : "r"(addr));
}
__device__ __forceinline__ void ldsm4t(u32 addr, u32& r0, u32& r1, u32& r2, u32& r3)
{
    asm volatile("ldmatrix.sync.aligned.m8n8.x4.trans.shared.b16 {%0,%1,%2,%3}, [%4];"
        : "=r"(r0), "=r"(r1), "=r"(r2), "=r"(r3) : "r"(addr));
}

__device__ __forceinline__ void mma_bf16(float* d, const u32* a, u32 b0, u32 b1)
{
    asm volatile(
        "mma.sync.aligned.m16n8k16.row.col.f32.bf16.bf16.f32 "
        "{%0,%1,%2,%3},{%4,%5,%6,%7},{%8,%9},{%0,%1,%2,%3};"
        : "+f"(d[0]), "+f"(d[1]), "+f"(d[2]), "+f"(d[3])
        : "r"(a[0]), "r"(a[1]), "r"(a[2]), "r"(a[3]), "r"(b0), "r"(b1));
}
__device__ __forceinline__ void mma_f16(float* d, const u32* a, u32 b0, u32 b1)
{
    asm volatile(
        "mma.sync.aligned.m16n8k16.row.col.f32.f16.f16.f32 "
        "{%0,%1,%2,%3},{%4,%5,%6,%7},{%8,%9},{%0,%1,%2,%3};"
        : "+f"(d[0]), "+f"(d[1]), "+f"(d[2]), "+f"(d[3])
        : "r"(a[0]), "r"(a[1]), "r"(a[2]), "r"(a[3]), "r"(b0), "r"(b1));
}

// pack two fp32 into bf16x2 word: first arg -> lower halfword
__device__ __forceinline__ u32 pack_bf(float lo, float hi)
{
    u32 r;
    asm("cvt.rn.bf16x2.f32 %0, %1, %2;" : "=r"(r) : "f"(hi), "f"(lo));
    return r;
}
__device__ __forceinline__ u32 pack_h2(float lo, float hi)
{
    __half2 h = __floats2half2_rn(lo, hi);
    return *(u32*)&h;
}

__device__ __forceinline__ float bf_round(float v)
{
    return __bfloat162float(__float2bfloat16(v));
}

__device__ __forceinline__ void split_write(bf16* h, bf16* l, size_t idx, float v)
{
    bf16 hh = __float2bfloat16(v);
    h[idx] = hh;
    l[idx] = __float2bfloat16(v - __bfloat162float(hh));
}

__device__ __forceinline__ void split_store2(bf16* h, bf16* l, size_t idx,
                                             float v0, float v1)
{
    float h0 = bf_round(v0), h1 = bf_round(v1);
    *(u32*)(h + idx) = pack_bf(h0, h1);
    *(u32*)(l + idx) = pack_bf(v0 - h0, v1 - h1);
}

// packed quad store of bf16 splits (idx % 4 == 0)
__device__ __forceinline__ void split_store4(bf16* h, bf16* l, size_t idx,
                                             float4 v)
{
    float h0 = bf_round(v.x), h1 = bf_round(v.y),
          h2 = bf_round(v.z), h3 = bf_round(v.w);
    *(uint2*)(h + idx) = make_uint2(pack_bf(h0, h1), pack_bf(h2, h3));
    *(uint2*)(l + idx) = make_uint2(pack_bf(v.x - h0, v.y - h1),
                                    pack_bf(v.z - h2, v.w - h3));
}

// ----------------------------------------------------------------------------
// Weight conversion: one contiguous segment -> bf16 hi/lo (n8 8-elem units)
// ----------------------------------------------------------------------------
__global__ void cvt_seg_kernel(const float* __restrict__ src,
                               bf16* __restrict__ h, bf16* __restrict__ l,
                               long long n8)
{
    for (long long i = (long long)blockIdx.x * 256 + threadIdx.x; i < n8;
         i += (long long)gridDim.x * 256) {
        const float4* xp = (const float4*)src + 2 * i;
        float4 a = xp[0], b = xp[1];
        float h0 = bf_round(a.x), h1 = bf_round(a.y),
              h2 = bf_round(a.z), h3 = bf_round(a.w),
              h4 = bf_round(b.x), h5 = bf_round(b.y),
              h6 = bf_round(b.z), h7 = bf_round(b.w);
        uint4 H, L;
        H.x = pack_bf(h0, h1); H.y = pack_bf(h2, h3);
        H.z = pack_bf(h4, h5); H.w = pack_bf(h6, h7);
        L.x = pack_bf(a.x - h0, a.y - h1); L.y = pack_bf(a.z - h2, a.w - h3);
        L.z = pack_bf(b.x - h4, b.y - h5); L.w = pack_bf(b.z - h6, b.w - h7);
        ((uint4*)h)[i] = H;
        ((uint4*)l)[i] = L;
    }
}

// cls_w2: [NE,100] -> [NE,112] zero-padded FP16 single (hi only; 1-term cls2)
__global__ void cvt_pad_kernel(const float* __restrict__ x,
                               bf16* __restrict__ h)
{
    int total = NE * 28;
    for (int i = blockIdx.x * 256 + threadIdx.x; i < total; i += gridDim.x * 256) {
        int r = i / 28, c4 = (i - r * 28) * 4;
        u32 ha = 0, hb = 0;
        if (c4 < 100) {
            float4 v = *(const float4*)(x + (size_t)r * 100 + c4);
            ha = pack_h2(v.x, v.y); hb = pack_h2(v.z, v.w);
        }
        size_t o = (size_t)r * KPAD + c4;
        *(uint2*)(h + o) = make_uint2(ha, hb);
    }
}

// ----------------------------------------------------------------------------
// Mention pooling (pos/mask int32), inline attention logits.
// ----------------------------------------------------------------------------
__global__ __launch_bounds__(256)
void pool_kernel(const float* __restrict__ lhs,
                 const int* __restrict__ pos,
                 const int* __restrict__ mask,
                 const float* __restrict__ aw,
                 float* __restrict__ x,
                 bf16* __restrict__ xh, bf16* __restrict__ xl)
{
    int bm = blockIdx.x;
    int b = bm >> 7;
    int t = threadIdx.x;
    __shared__ float dots[LL];
    __shared__ float ws[LL];
    __shared__ int s_nv;

    {
        int l = t >> 3, sub = t & 7;
        const float* row = lhs + ((size_t)b * SS + l) * DD;
        float p = 0.f;
        for (int j = sub; j < DD; j += 8) p += row[j] * aw[j];
        #pragma unroll
        for (int o = 4; o; o >>= 1) p += __shfl_xor_sync(~0u, p, o);
        if (sub == 0) dots[l] = p;
    }
    __syncthreads();

    if (t < 32) {
        int p = pos[(size_t)bm * LL + t];
        unsigned bits = __ballot_sync(0xffffffffu, p != -1);
        int nv;
        if (mask[bm] == 0) nv = 0;
        else if (~bits == 0u) nv = 32;
        else nv = __ffs(~bits) - 1;
        float logit = (t < nv) ? dots[t] : 0.f;
        float mx = logit;
        #pragma unroll
        for (int o = 16; o; o >>= 1) mx = fmaxf(mx, __shfl_xor_sync(~0u, mx, o));
        float e = expf(logit - mx);
        float s = e;
        #pragma unroll
        for (int o = 16; o; o >>= 1) s += __shfl_xor_sync(~0u, s, o);
        ws[t] = e / s;
        if (t == 0) s_nv = nv;
    }
    __syncthreads();
    int nv = s_nv;
    for (int d = t; d < DD; d += 256) {
        float acc = 0.f;
        for (int l = 0; l < nv; l++)
            acc += ws[l] * lhs[((size_t)b * SS + l) * DD + d];
        size_t idx = (size_t)bm * DD + d;
        x[idx] = acc;
        split_write(xh, xl, idx, acc);
    }
}

// ----------------------------------------------------------------------------
// Tensor-core split NT GEMM (original axis order).
// ----------------------------------------------------------------------------
template<int TM, int TN, int RELU, int SPLIT, int PREC, int OCC>
__global__ __launch_bounds__(256, OCC)
void gemm_tc(const bf16* __restrict__ Ah, const bf16* __restrict__ Al,
             const bf16* __restrict__ Bh, const bf16* __restrict__ Bl,
             const float* __restrict__ bias,
             float* __restrict__ C, bf16* __restrict__ Ch, bf16* __restrict__ Cl,
             int M, int N, int lda, int ldb, int Klen, int ldout, int padN)
{
    constexpr int MI  = TM / 64;
    constexpr int NJW = TN / 16;
    constexpr int NA  = (PREC == 0) ? 2 : 1;
    constexpr int NB  = (PREC == 2) ? 1 : 2;
    constexpr int ASZ = TM * 64;
    constexpr int BSZ = TN * 64;
    constexpr int BUF = NA * ASZ + NB * BSZ;

    extern __shared__ char smem[];
    const u32 base = smem_u32(smem);
    const int t = threadIdx.x, lane = t & 31, warp = t >> 5;
    const int mBase = blockIdx.y * TM, nBase = blockIdx.x * TN;
    const int kOff = blockIdx.z * Klen;
    const int wm = (warp >> 1) * (TM / 4), wn = (warp & 1) * (TN / 2);
    const int ar0 = wm + (lane & 15);
    const int ahi = lane >> 4;
    const int br0 = wn + (lane & 7) + ((lane >> 4) << 3);
    const int bhi = (lane >> 3) & 1;

    float acc[MI][NJW][4];
    #pragma unroll
    for (int mi = 0; mi < MI; mi++)
        #pragma unroll
        for (int nj = 0; nj < NJW; nj++)
            #pragma unroll
            for (int r = 0; r < 4; r++) acc[mi][nj][r] = 0.f;

    const int S = (Klen + 31) / 32;

    auto loadSlab = [&](int s) {
        const int k0 = s * 32;
        const u32 bb = base + (s % 3) * BUF;
        #pragma unroll
        for (int p = 0; p < TM / 64; p++) {
            int c = p * 256 + t, row = c >> 2, ch = c & 3;
            int kk = k0 + ch * 8;
            int avail = Klen - kk;
            int sz = (avail >= 8) ? 16 : (avail > 0 ? avail * 2 : 0);
            u32 off = row * 64 + ((u32)(ch ^ ((row >> 1) & 3)) << 4);
            cp_async16(bb + off, Ah + (size_t)(mBase + row) * lda + kOff + kk, sz);
            if (PREC == 0)
                cp_async16(bb + ASZ + off, Al + (size_t)(mBase + row) * lda + kOff + kk, sz);
        }
        #pragma unroll
        for (int p = 0; p < TN / 64; p++) {
            int c = p * 256 + t, row = c >> 2, ch = c & 3;
            int kk = k0 + ch * 8;
            int avail = Klen - kk;
            int sz = (avail >= 8) ? 16 : (avail > 0 ? avail * 2 : 0);
            if (nBase + row >= N) sz = 0;
            u32 off = row * 64 + ((u32)(ch ^ ((row >> 1) & 3)) << 4);
            cp_async16(bb + NA * ASZ + off, Bh + (size_t)(nBase + row) * ldb + kOff + kk, sz);
            if (PREC < 2)
                cp_async16(bb + NA * ASZ + BSZ + off, Bl + (size_t)(nBase + row) * ldb + kOff + kk, sz);
        }
    };

    loadSlab(0);
    CP_COMMIT();
    if (S > 1) loadSlab(1);
    CP_COMMIT();

    for (int s = 0; s < S; s++) {
        CP_WAIT1();
        __syncthreads();
        if (s + 2 < S) loadSlab(s + 2);
        CP_COMMIT();

        const u32 bb = base + (s % 3) * BUF;
        const u32 aB0 = bb, aB1 = bb + ASZ;
        const u32 bB0 = bb + NA * ASZ, bB1 = bb + NA * ASZ + BSZ;

        #pragma unroll
        for (int ks = 0; ks < 2; ks++) {
            u32 ahf[MI][4], alf[MI][4];
            #pragma unroll
            for (int mi = 0; mi < MI; mi++) {
                int row = ar0 + mi * 16;
                u32 off = row * 64 + ((u32)((ks * 2 + ahi) ^ ((row >> 1) & 3)) << 4);
                ldsm4(aB0 + off, ahf[mi][0], ahf[mi][1], ahf[mi][2], ahf[mi][3]);
                if (PREC == 0)
                    ldsm4(aB1 + off, alf[mi][0], alf[mi][1], alf[mi][2], alf[mi][3]);
            }
            #pragma unroll
            for (int j = 0; j < NJW / 2; j++) {
                int row = br0 + j * 16;
                u32 off = row * 64 + ((u32)((ks * 2 + bhi) ^ ((row >> 1) & 3)) << 4);
                u32 b0, b1, b2, b3, l0, l1, l2, l3;
                ldsm4(bB0 + off, b0, b1, b2, b3);
                if (PREC < 2) ldsm4(bB1 + off, l0, l1, l2, l3);
                if (PREC == 0) {
                    #pragma unroll
                    for (int mi = 0; mi < MI; mi++) {
                        mma_bf16(acc[mi][2 * j],     ahf[mi], b0, b1);
                        mma_bf16(acc[mi][2 * j + 1], ahf[mi], b2, b3);
                    }
                    #pragma unroll
                    for (int mi = 0; mi < MI; mi++) {
                        mma_bf16(acc[mi][2 * j],     ahf[mi], l0, l1);
                        mma_bf16(acc[mi][2 * j + 1], ahf[mi], l2, l3);
                    }
                    #pragma unroll
                    for (int mi = 0; mi < MI; mi++) {
                        mma_bf16(acc[mi][2 * j],     alf[mi], b0, b1);
                        mma_bf16(acc[mi][2 * j + 1], alf[mi], b2, b3);
                    }
                } else if (PREC == 1) {
                    #pragma unroll
                    for (int mi = 0; mi < MI; mi++) {
                        mma_f16(acc[mi][2 * j],     ahf[mi], b0, b1);
                        mma_f16(acc[mi][2 * j + 1], ahf[mi], b2, b3);
                    }
                    #pragma unroll
                    for (int mi = 0; mi < MI; mi++) {
                        mma_f16(acc[mi][2 * j],     ahf[mi], l0, l1);
                        mma_f16(acc[mi][2 * j + 1], ahf[mi], l2, l3);
                    }
                } else {
                    #pragma unroll
                    for (int mi = 0; mi < MI; mi++) {
                        mma_f16(acc[mi][2 * j],     ahf[mi], b0, b1);
                        mma_f16(acc[mi][2 * j + 1], ahf[mi], b2, b3);
                    }
                }
            }
        }
    }

    // epilogue
    float* Cz = C + (size_t)blockIdx.z * M * ldout;
    const int g = lane >> 2, tg = lane & 3;
    #pragma unroll
    for (int mi = 0; mi < MI; mi++) {
        int row0 = mBase + wm + mi * 16 + g;
        #pragma unroll
        for (int nj = 0; nj < NJW; nj++) {
            int col0 = nBase + wn + nj * 8 + 2 * tg;
            if (col0 < padN) {
                #pragma unroll
                for (int rr = 0; rr < 2; rr++) {
                    int row = row0 + rr * 8;
                    float v0 = 0.f, v1 = 0.f;
                    if (col0 < N) {
                        v0 = acc[mi][nj][rr * 2 + 0] + (bias ? bias[col0] : 0.f);
                        v1 = acc[mi][nj][rr * 2 + 1] + (bias ? bias[col0 + 1] : 0.f);
                        if (RELU) { v0 = fmaxf(v0, 0.f); v1 = fmaxf(v1, 0.f); }
                    }
                    size_t idx = (size_t)row * ldout + col0;
                    if (SPLIT == 1)      split_store2(Ch, Cl, idx, v0, v1);
                    else if (SPLIT == 2) *(u32*)(Ch + idx) = pack_h2(v0, v1);
                    else                 *(float2*)(Cz + idx) = make_float2(v0, v1);
                }
            }
        }
    }
}

// ----------------------------------------------------------------------------
// Fused attention, Q-split: one CTA per (b,h,half). 4 warps x 16 Q-rows = 64.
// 128 threads, 2 CTAs/SM. Full K/V tiles; Q covers rows [half*64, half*64+64).
// ----------------------------------------------------------------------------
#define SMEMATT (2 * 8192 + 4 * 16384)     // 81920

__global__ __launch_bounds__(128, 2)
void attn_fused(const bf16* __restrict__ qkvh, const bf16* __restrict__ qkvl,
                bf16* __restrict__ aoh, bf16* __restrict__ aol)
{
    extern __shared__ char smem[];
    const u32 base = smem_u32(smem);
    const int t = threadIdx.x, lane = t & 31, warp = t >> 5;
    const int bh2 = blockIdx.x, bh = bh2 >> 1, half = bh2 & 1;
    const int b = bh / HH, h = bh % HH;
    const size_t rowBase = (size_t)b * MM;
    const int qOff = half * 64;
    const int g = lane >> 2, tg = lane & 3;

    const u32 sQh = base, sQl = base + 8192;
    const u32 sKh = base + 16384, sKl = base + 32768;
    const u32 sVh = base + 49152, sVl = base + 65536;

    #pragma unroll
    for (int m = 0; m < 2; m++) {
        const bf16* src = m ? qkvl : qkvh;
        u32 dst = m ? sQl : sQh;
        #pragma unroll
        for (int p = 0; p < 4; p++) {
            int c = p * 128 + t;
            int row = c >> 3, ch = c & 7;
            u32 off = row * 128 + ((u32)(ch ^ (row & 7)) << 4);
            cp_async16(dst + off,
                       src + (rowBase + qOff + row) * (3 * DD) + h * HD + ch * 8, 16);
        }
    }
    #pragma unroll
    for (int m = 0; m < 4; m++) {
        const bf16* src = (m & 1) ? qkvl : qkvh;
        int colOff = (1 + (m >> 1)) * DD + h * HD;   // K then V
        u32 dst = (m == 0) ? sKh : (m == 1) ? sKl : (m == 2) ? sVh : sVl;
        #pragma unroll
        for (int p = 0; p < 8; p++) {
            int c = p * 128 + t;
            int row = c >> 3, ch = c & 7;
            u32 off = row * 128 + ((u32)(ch ^ (row & 7)) << 4);
            cp_async16(dst + off,
                       src + (rowBase + row) * (3 * DD) + colOff + ch * 8, 16);
        }
    }
    CP_COMMIT(); CP_WAIT0();
    __syncthreads();

    const int m0 = warp * 16;

    float acc[16][4];
    #pragma unroll
    for (int nj = 0; nj < 16; nj++)
        #pragma unroll
        for (int r = 0; r < 4; r++) acc[nj][r] = 0.f;

    const int tile = lane >> 3, wr = lane & 7;
    #pragma unroll
    for (int kk = 0; kk < 4; kk++) {
        u32 qh4[4], ql4[4];
        {
            int row = m0 + wr + (tile & 1) * 8;
            int ch = kk * 2 + (tile >> 1);
            u32 off = row * 128 + ((u32)(ch ^ (row & 7)) << 4);
            ldsm4(sQh + off, qh4[0], qh4[1], qh4[2], qh4[3]);
            ldsm4(sQl + off, ql4[0], ql4[1], ql4[2], ql4[3]);
        }
        #pragma unroll
        for (int nj2 = 0; nj2 < 8; nj2++) {
            int row = nj2 * 16 + wr + (tile >> 1) * 8;
            int ch = kk * 2 + (tile & 1);
            u32 off = row * 128 + ((u32)(ch ^ (row & 7)) << 4);
            u32 b0, b1, b2, b3, l0, l1, l2, l3;
            ldsm4(sKh + off, b0, b1, b2, b3);
            ldsm4(sKl + off, l0, l1, l2, l3);
            mma_bf16(acc[2 * nj2],     qh4, b0, b1);
            mma_bf16(acc[2 * nj2 + 1], qh4, b2, b3);
            mma_bf16(acc[2 * nj2],     qh4, l0, l1);
            mma_bf16(acc[2 * nj2 + 1], qh4, l2, l3);
            mma_bf16(acc[2 * nj2],     ql4, b0, b1);
            mma_bf16(acc[2 * nj2 + 1], ql4, b2, b3);
        }
    }

    {
        float mx0 = -1e30f, mx1 = -1e30f;
        #pragma unroll
        for (int nj = 0; nj < 16; nj++) {
            acc[nj][0] *= 0.125f; acc[nj][1] *= 0.125f;
            acc[nj][2] *= 0.125f; acc[nj][3] *= 0.125f;
            mx0 = fmaxf(mx0, fmaxf(acc[nj][0], acc[nj][1]));
            mx1 = fmaxf(mx1, fmaxf(acc[nj][2], acc[nj][3]));
        }
        mx0 = fmaxf(mx0, __shfl_xor_sync(~0u, mx0, 1));
        mx0 = fmaxf(mx0, __shfl_xor_sync(~0u, mx0, 2));
        mx1 = fmaxf(mx1, __shfl_xor_sync(~0u, mx1, 1));
        mx1 = fmaxf(mx1, __shfl_xor_sync(~0u, mx1, 2));
        float s0 = 0.f, s1 = 0.f;
        #pragma unroll
        for (int nj = 0; nj < 16; nj++) {
            acc[nj][0] = expf(acc[nj][0] - mx0);
            acc[nj][1] = expf(acc[nj][1] - mx0);
            acc[nj][2] = expf(acc[nj][2] - mx1);
            acc[nj][3] = expf(acc[nj][3] - mx1);
            s0 += acc[nj][0] + acc[nj][1];
            s1 += acc[nj][2] + acc[nj][3];
        }
        s0 += __shfl_xor_sync(~0u, s0, 1);
        s0 += __shfl_xor_sync(~0u, s0, 2);
        s1 += __shfl_xor_sync(~0u, s1, 1);
        s1 += __shfl_xor_sync(~0u, s1, 2);
        float i0 = 1.f / s0, i1 = 1.f / s1;
        #pragma unroll
        for (int nj = 0; nj < 16; nj++) {
            acc[nj][0] *= i0; acc[nj][1] *= i0;
            acc[nj][2] *= i1; acc[nj][3] *= i1;
        }
    }

    float o[8][4];
    #pragma unroll
    for (int nj = 0; nj < 8; nj++)
        #pragma unroll
        for (int r = 0; r < 4; r++) o[nj][r] = 0.f;

    #pragma unroll
    for (int j = 0; j < 8; j++) {
        u32 pa_h[4], pa_l[4];
        #pragma unroll
        for (int q = 0; q < 2; q++) {
            float p0 = acc[2 * j + q][0], p1 = acc[2 * j + q][1];
            float p2 = acc[2 * j + q][2], p3 = acc[2 * j + q][3];
            float h0 = bf_round(p0), h1 = bf_round(p1);
            float h2 = bf_round(p2), h3 = bf_round(p3);
            pa_h[0 + 2 * q] = pack_bf(h0, h1);
            pa_h[1 + 2 * q] = pack_bf(h2, h3);
            pa_l[0 + 2 * q] = pack_bf(p0 - h0, p1 - h1);
            pa_l[1 + 2 * q] = pack_bf(p2 - h2, p3 - h3);
        }
        #pragma unroll
        for (int c2 = 0; c2 < 4; c2++) {
            int row = j * 16 + wr + (tile & 1) * 8;
            int ch = 2 * c2 + (tile >> 1);
            u32 off = row * 128 + ((u32)(ch ^ (row & 7)) << 4);
            u32 v0, v1, v2, v3, w0, w1, w2, w3;
            ldsm4t(sVh + off, v0, v1, v2, v3);
            ldsm4t(sVl + off, w0, w1, w2, w3);
            mma_bf16(o[2 * c2],     pa_h, v0, v1);
            mma_bf16(o[2 * c2 + 1], pa_h, v2, v3);
            mma_bf16(o[2 * c2],     pa_h, w0, w1);
            mma_bf16(o[2 * c2 + 1], pa_h, w2, w3);
            mma_bf16(o[2 * c2],     pa_l, v0, v1);
            mma_bf16(o[2 * c2 + 1], pa_l, v2, v3);
        }
    }

    {
        size_t gr = rowBase + qOff + m0 + g;
        #pragma unroll
        for (int nj = 0; nj < 8; nj++) {
            int col = h * HD + nj * 8 + 2 * tg;
            split_store2(aoh, aol, gr * DD + col, o[nj][0], o[nj][1]);
            split_store2(aoh, aol, (gr + 8) * DD + col, o[nj][2], o[nj][3]);
        }
    }
}

// ----------------------------------------------------------------------------
// x = LayerNorm(x + d0 + d1 + bias) * w + b; writes bf16 split of x.
// float4 vectorized: 192 quads per row; 256 threads -> t<192 do one quad of
// each third? Use 192 active lanes x 4 quads... simpler: each thread handles
// one quad strided (192 quads, 256 threads -> threads 0..191 active per pass,
// single pass of 192). To keep all 256 threads busy use 3 passes of 64 quads.
// ----------------------------------------------------------------------------
__global__ __launch_bounds__(192)
void add_ln_kernel(float* __restrict__ x,
                   const float* __restrict__ d0p, const float* __restrict__ d1p,
                   const float* __restrict__ bias,
                   const float* __restrict__ w, const float* __restrict__ b,
                   bf16* __restrict__ xh, bf16* __restrict__ xl)
{
    int row = blockIdx.x, t = threadIdx.x;          // 192 threads, 1 quad each
    float4* xp = (float4*)(x + (size_t)row * DD);
    const float4* a0 = (const float4*)(d0p + (size_t)row * DD);
    const float4* a1 = (const float4*)(d1p + (size_t)row * DD);
    const float4* bi = (const float4*)bias;
    float4 v = xp[t], q0 = a0[t], q1 = a1[t], qb = bi[t];
    v.x += q0.x + q1.x + qb.x;
    v.y += q0.y + q1.y + qb.y;
    v.z += q0.z + q1.z + qb.z;
    v.w += q0.w + q1.w + qb.w;

    float s = v.x + v.y + v.z + v.w;
    __shared__ float red[6];
    #pragma unroll
    for (int o = 16; o; o >>= 1) s += __shfl_xor_sync(~0u, s, o);
    if ((t & 31) == 0) red[t >> 5] = s;
    __syncthreads();
    float tot = red[0] + red[1] + red[2] + red[3] + red[4] + red[5];
    float mu = tot * (1.f / 768.f);
    float d0 = v.x - mu, d1 = v.y - mu, d2 = v.z - mu, d3 = v.w - mu;
    float q = d0 * d0 + d1 * d1 + d2 * d2 + d3 * d3;
    #pragma unroll
    for (int o = 16; o; o >>= 1) q += __shfl_xor_sync(~0u, q, o);
    __syncthreads();
    if ((t & 31) == 0) red[t >> 5] = q;
    __syncthreads();
    float qt = red[0] + red[1] + red[2] + red[3] + red[4] + red[5];
    float inv = rsqrtf(qt * (1.f / 768.f) + 1e-5f);
    const float4* wv = (const float4*)w;
    const float4* bv = (const float4*)b;
    float4 ww = wv[t], bb = bv[t];
    float4 o4;
    o4.x = d0 * inv * ww.x + bb.x;
    o4.y = d1 * inv * ww.y + bb.y;
    o4.z = d2 * inv * ww.z + bb.z;
    o4.w = d3 * inv * ww.w + bb.w;
    xp[t] = o4;
    split_store4(xh, xl, (size_t)row * DD + t * 4, o4);
}

// ----------------------------------------------------------------------------
// Host-side launch
// ----------------------------------------------------------------------------
template<typename T>
static T* sym(const void* s)
{
    void* p = nullptr;
    cudaGetSymbolAddress(&p, s);
    return (T*)p;
}

#define SMEM_G(TM, TN, NA, NB) (3 * ((NA) * (TM) * 64 + (NB) * (TN) * 64))

extern "C" void kernel_launch(void* const* d_in, const int* in_sizes, int n_in,
                              void* d_out, int out_size)
{
    static const long long want[20] = {
        6291456LL, 65536LL, 2048LL, 768LL, 1LL,
        7077888LL, 9216LL, 2359296LL, 3072LL, 3072LL, 3072LL,
        9437184LL, 12288LL, 9437184LL, 3072LL, 3072LL, 3072LL,
        76800LL, 5000000LL, 50000LL
    };
    const void* slot[20];
    bool used[64];
    for (int i = 0; i < 20; i++) slot[i] = nullptr;
    for (int i = 0; i < n_in && i < 64; i++) used[i] = false;
    for (int w = 0; w < 20; w++) {
        for (int i = 0; i < n_in && i < 64; i++) {
            if (!used[i] && (long long)in_sizes[i] == want[w]) {
                slot[w] = d_in[i];
                used[i] = true;
                break;
            }
        }
    }
    if (!slot[0]) {
        for (int w = 0; w < 20 && w < n_in; w++) slot[w] = d_in[w];
    }

    const float* lhs    = (const float*)slot[0];
    const int*   pos    = (const int*)slot[1];
    const int*   mask   = (const int*)slot[2];
    const float* attn_w = (const float*)slot[3];
    const float* qkv_w  = (const float*)slot[5];
    const float* qkv_b  = (const float*)slot[6];
    const float* out_w  = (const float*)slot[7];
    const float* out_b  = (const float*)slot[8];
    const float* ln1_w  = (const float*)slot[9];
    const float* ln1_b  = (const float*)slot[10];
    const float* ff1_w  = (const float*)slot[11];
    const float* ff1_b  = (const float*)slot[12];
    const float* ff2_w  = (const float*)slot[13];
    const float* ff2_b  = (const float*)slot[14];
    const float* ln2_w  = (const float*)slot[15];
    const float* ln2_b  = (const float*)slot[16];
    const float* cls_w1 = (const float*)slot[17];
    const float* cls_w2 = (const float*)slot[18];
    const float* cls_b2 = (const float*)slot[19];
    float* out = (float*)d_out;

    float* x   = sym<float>(g_x);
    float* tmp = sym<float>(g_tmp);
    bf16*  wh  = sym<bf16>(g_wh);
    bf16*  wl  = sym<bf16>(g_wl);
    bf16*  ah  = sym<bf16>(g_ah);
    bf16*  al  = sym<bf16>(g_al);
    bf16*  bh2 = sym<bf16>(g_bh);
    bf16*  bl2 = sym<bf16>(g_bl);

    cudaFuncSetAttribute(gemm_tc<128, 128, 0, 1, 0, 2>, cudaFuncAttributeMaxDynamicSharedMemorySize, SMEM_G(128, 128, 2, 2));
    cudaFuncSetAttribute(gemm_tc<128, 128, 1, 1, 0, 2>, cudaFuncAttributeMaxDynamicSharedMemorySize, SMEM_G(128, 128, 2, 2));
    cudaFuncSetAttribute(gemm_tc<128, 64, 0, 0, 0, 3>,  cudaFuncAttributeMaxDynamicSharedMemorySize, SMEM_G(128, 64, 2, 2));
    cudaFuncSetAttribute(gemm_tc<128, 64, 0, 2, 0, 3>,  cudaFuncAttributeMaxDynamicSharedMemorySize, SMEM_G(128, 64, 2, 2));
    cudaFuncSetAttribute(gemm_tc<128, 128, 0, 0, 2, 2>, cudaFuncAttributeMaxDynamicSharedMemorySize, SMEM_G(128, 128, 1, 1));
    cudaFuncSetAttribute(attn_fused, cudaFuncAttributeMaxDynamicSharedMemorySize, SMEMATT);

    // --- prologue pipeline ---
    cudaStream_t s2;
    cudaStreamCreateWithFlags(&s2, cudaStreamNonBlocking);
    cudaEvent_t eFork, ePool, eJoin;
    cudaEventCreateWithFlags(&eFork, cudaEventDisableTiming);
    cudaEventCreateWithFlags(&ePool, cudaEventDisableTiming);
    cudaEventCreateWithFlags(&eJoin, cudaEventDisableTiming);

    cudaEventRecord(eFork, 0);
    cudaStreamWaitEvent(s2, eFork, 0);
    pool_kernel<<<ROWS, 256, 0, s2>>>(lhs, pos, mask, attn_w, x, ah, al);
    cudaEventRecord(ePool, s2);
    cvt_seg_kernel<<<2048, 256, 0, s2>>>(out_w,  wh + OW_OUT,  wl + OW_OUT,  294912);
    cvt_seg_kernel<<<4096, 256, 0, s2>>>(ff1_w,  wh + OW_FF1,  wl + OW_FF1,  1179648);
    cvt_seg_kernel<<<4096, 256, 0, s2>>>(ff2_w,  wh + OW_FF2,  wl + OW_FF2,  1179648);
    cvt_seg_kernel<<<64,   256, 0, s2>>>(cls_w1, wh + OW_CLS1, wl + OW_CLS1, 9600);
    cvt_pad_kernel<<<2736, 256, 0, s2>>>(cls_w2, wh + OW_CLS2);
    cudaEventRecord(eJoin, s2);

    cvt_seg_kernel<<<3456, 256>>>(qkv_w, wh + OW_QKV, wl + OW_QKV, 884736);
    cudaStreamWaitEvent(0, ePool, 0);

    // --- transformer layers ---
    for (int i = 0; i < NL; i++) {
        gemm_tc<128, 128, 0, 1, 0, 2><<<dim3(18, 16, 1), 256, SMEM_G(128, 128, 2, 2)>>>(
            ah, al, wh + OW_QKV + (size_t)i * 3 * DD * DD,
            wl + OW_QKV + (size_t)i * 3 * DD * DD,
            qkv_b + (size_t)i * 3 * DD, nullptr, bh2, bl2,
            ROWS, 3 * DD, DD, DD, DD, 3 * DD, 3 * DD);
        attn_fused<<<BB * HH * 2, 128, SMEMATT>>>(bh2, bl2, ah, al);
        if (i == 0) cudaStreamWaitEvent(0, eJoin, 0);
        gemm_tc<128, 64, 0, 0, 0, 3><<<dim3(12, 16, 2), 256, SMEM_G(128, 64, 2, 2)>>>(
            ah, al, wh + OW_OUT + (size_t)i * DD * DD,
            wl + OW_OUT + (size_t)i * DD * DD,
            nullptr, tmp, nullptr, nullptr,
            ROWS, DD, DD, DD, DD / 2, DD, DD);
        add_ln_kernel<<<ROWS, 192>>>(x, tmp, tmp + (size_t)ROWS * DD,
                                     out_b + (size_t)i * DD,
                                     ln1_w + (size_t)i * DD, ln1_b + (size_t)i * DD,
                                     ah, al);
        // ff1: TN=128/OCC=2 -> 384 CTAs = 1.30 waves of 296
        gemm_tc<128, 128, 1, 1, 0, 2><<<dim3(24, 16, 1), 256, SMEM_G(128, 128, 2, 2)>>>(
            ah, al, wh + OW_FF1 + (size_t)i * DFF * DD,
            wl + OW_FF1 + (size_t)i * DFF * DD,
            ff1_b + (size_t)i * DFF, nullptr, bh2, bl2,
            ROWS, DFF, DD, DD, DD, DFF, DFF);
        gemm_tc<128, 64, 0, 0, 0, 3><<<dim3(12, 16, 2), 256, SMEM_G(128, 64, 2, 2)>>>(
            bh2, bl2, wh + OW_FF2 + (size_t)i * DD * DFF,
            wl + OW_FF2 + (size_t)i * DD * DFF,
            nullptr, tmp, nullptr, nullptr,
            ROWS, DD, DFF, DFF, DFF / 2, DD, DD);
        add_ln_kernel<<<ROWS, 192>>>(x, tmp, tmp + (size_t)ROWS * DD,
                                     ff2_b + (size_t)i * DD,
                                     ln2_w + (size_t)i * DD, ln2_b + (size_t)i * DD,
                                     ah, al);
    }

    // --- classifier head ---
    gemm_tc<128, 64, 0, 2, 0, 3><<<dim3(2, 16, 1), 256, SMEM_G(128, 64, 2, 2)>>>(
        ah, al, wh + OW_CLS1, wl + OW_CLS1, nullptr,
        nullptr, bh2, nullptr, ROWS, 100, DD, DD, DD, KPAD, KPAD);
    gemm_tc<128, 128, 0, 0, 2, 2><<<dim3((NE + 127) / 128, 16, 1), 256, SMEM_G(128, 128, 1, 1)>>>(
        bh2, nullptr, wh + OW_CLS2, nullptr, cls_b2,
        out, nullptr, nullptr, ROWS, NE, KPAD, KPAD, KPAD, NE, NE);
}